// round 12
// baseline (speedup 1.0000x reference)
#include <cuda_runtime.h>

#define TSTEPS   512
#define NTHREADS 512

// SMEM geometry (floats)
#define WST  76          // weight row stride: k' 0..31 at kh*36, pad to 76
#define IST  72          // input row per batch: kh*36 + k' (x|h), pad to 72
#define GSB  132         // gs per-batch stride
#define GSK  2128        // gs kh-plane stride: 16*132 + 16 (= 4 mod 8 chunks)
#define GSG  (2*GSK)     // gs per group (2 kh planes)

#define OFF_W    0           // 2 * 128*76 = 19456
#define WLAY     (128*WST)
#define OFF_GS   19456       // 4 groups * 4256 = 17024
#define OFF_IN0  36480       // 32*72  L0 input [x | h0]
#define OFF_I1A  38784       // 32*72  L1 input buffer A [h0 | h1]
#define OFF_I1B  41088       // 32*72  L1 input buffer B [h0 | h1]
#define OFF_B0   43392       // 128
#define OFF_B1   43520       // 128
#define OFF_W1S  43648       // 32
#define OFF_B1S  43680       // 32
#define OFF_W2S  43712       // 64
#define SMEM_FLOATS 43776
#define SMEM_BYTES  (SMEM_FLOATS * 4)   // 175104

typedef unsigned long long ull;

__device__ __forceinline__ void bar_sync(int id, int cnt) {
    asm volatile("bar.sync %0, %1;" :: "r"(id), "r"(cnt) : "memory");
}
__device__ __forceinline__ void bar_arrive(int id, int cnt) {
    asm volatile("bar.arrive %0, %1;" :: "r"(id), "r"(cnt) : "memory");
}
__device__ __forceinline__ float sum2(ull v) {
    float lo, hi;
    asm("mov.b64 {%0,%1}, %2;" : "=f"(lo), "=f"(hi) : "l"(v));
    return lo + hi;
}
__device__ __forceinline__ void ffma2(ull& d, ull a, ull b) {
    asm("fma.rn.f32x2 %0, %1, %2, %0;" : "+l"(d) : "l"(a), "l"(b));
}
__device__ __forceinline__ float sigm(float v) {
    float e = __expf(-v);
    return __fdividef(1.0f, 1.0f + e);
}
__device__ __forceinline__ float tanh_(float v) {
    float e = __expf(-2.0f * v);
    return __fdividef(2.0f, 1.0f + e) - 1.0f;
}

// Gate partial-GEMM: thread computes 8 rows (rg*8..+7) x 4 batches (bq+4i of a
// 16-batch half) over one 32-k half (kh). inb pre-offset to half base + kh.
__device__ __forceinline__ void gate_phase(const float* __restrict__ Wb,
                                           const float* __restrict__ inb,
                                           float* __restrict__ gsb,
                                           int rg, int bq) {
    ull acc[8][4];
#pragma unroll
    for (int j = 0; j < 8; j++)
#pragma unroll
        for (int i = 0; i < 4; i++) acc[j][i] = 0ull;

    const float* wr = Wb + rg * 8 * WST;
#pragma unroll
    for (int kq = 0; kq < 8; kq++) {
        ulonglong2 in[4];
#pragma unroll
        for (int i = 0; i < 4; i++)
            in[i] = *(const ulonglong2*)(inb + (bq + 4 * i) * IST + kq * 4);
#pragma unroll
        for (int j = 0; j < 8; j++) {
            ulonglong2 w = *(const ulonglong2*)(wr + j * WST + kq * 4);
#pragma unroll
            for (int i = 0; i < 4; i++) {
                ffma2(acc[j][i], w.x, in[i].x);
                ffma2(acc[j][i], w.y, in[i].y);
            }
        }
    }
#pragma unroll
    for (int i = 0; i < 4; i++) {
        float4 v0, v1;
        v0.x = sum2(acc[0][i]); v0.y = sum2(acc[1][i]);
        v0.z = sum2(acc[2][i]); v0.w = sum2(acc[3][i]);
        v1.x = sum2(acc[4][i]); v1.y = sum2(acc[5][i]);
        v1.z = sum2(acc[6][i]); v1.w = sum2(acc[7][i]);
        float* p = gsb + (bq + 4 * i) * GSB + rg * 8;
        *(float4*)p       = v0;
        *(float4*)(p + 4) = v1;
    }
}

// Gate partials (2 kh planes) -> activations -> c/h update for 4 units.
__device__ __forceinline__ float4 do_update(const float* gu0, const float* gu1,
                                            float4 bzi, float4 bzf, float4 bzg, float4 bzo,
                                            float& c0, float& c1, float& c2, float& c3) {
    float4 pi0 = *(const float4*)(gu0 + 0),  pi1 = *(const float4*)(gu1 + 0);
    float4 pf0 = *(const float4*)(gu0 + 32), pf1 = *(const float4*)(gu1 + 32);
    float4 pg0 = *(const float4*)(gu0 + 64), pg1 = *(const float4*)(gu1 + 64);
    float4 po0 = *(const float4*)(gu0 + 96), po1 = *(const float4*)(gu1 + 96);
    float iv0 = sigm(pi0.x + pi1.x + bzi.x), iv1 = sigm(pi0.y + pi1.y + bzi.y);
    float iv2 = sigm(pi0.z + pi1.z + bzi.z), iv3 = sigm(pi0.w + pi1.w + bzi.w);
    float fv0 = sigm(pf0.x + pf1.x + bzf.x), fv1 = sigm(pf0.y + pf1.y + bzf.y);
    float fv2 = sigm(pf0.z + pf1.z + bzf.z), fv3 = sigm(pf0.w + pf1.w + bzf.w);
    float gv0 = tanh_(pg0.x + pg1.x + bzg.x), gv1 = tanh_(pg0.y + pg1.y + bzg.y);
    float gv2 = tanh_(pg0.z + pg1.z + bzg.z), gv3 = tanh_(pg0.w + pg1.w + bzg.w);
    float ov0 = sigm(po0.x + po1.x + bzo.x), ov1 = sigm(po0.y + po1.y + bzo.y);
    float ov2 = sigm(po0.z + po1.z + bzo.z), ov3 = sigm(po0.w + po1.w + bzo.w);
    c0 = fmaf(fv0, c0, iv0 * gv0);
    c1 = fmaf(fv1, c1, iv1 * gv1);
    c2 = fmaf(fv2, c2, iv2 * gv2);
    c3 = fmaf(fv3, c3, iv3 * gv3);
    float4 h;
    h.x = ov0 * tanh_(c0);
    h.y = ov1 * tanh_(c1);
    h.z = ov2 * tanh_(c2);
    h.w = ov3 * tanh_(c3);
    return h;
}

__global__ void __launch_bounds__(NTHREADS, 1)
lstm_fused_kernel(const float* __restrict__ tensor,
                  const float* __restrict__ w1,   const float* __restrict__ b1,
                  const float* __restrict__ Wih0, const float* __restrict__ Whh0,
                  const float* __restrict__ bih0, const float* __restrict__ bhh0,
                  const float* __restrict__ Wih1, const float* __restrict__ Whh1,
                  const float* __restrict__ bih1, const float* __restrict__ bhh1,
                  const float* __restrict__ w2,   const float* __restrict__ b2,
                  float* __restrict__ out) {
    extern __shared__ float smem[];
    float* in0  = smem + OFF_IN0;
    float* in1a = smem + OFF_I1A;
    float* in1b = smem + OFF_I1B;

    const int tid = threadIdx.x;
    const int lay = tid >> 8;            // 0: layer0 warps, 1: layer1 warps
    const int hb  = (tid >> 7) & 1;      // batch half 0/1
    const int gid = (lay << 1) | hb;     // group 0..3
    const int u   = tid & 127;
    // Gate mapping within group
    const int kh = u & 1;
    const int bq = (u >> 1) & 3;
    const int rg = u >> 3;               // 0..15
    // Update mapping within group
    const int ubh = u >> 3;              // batch-in-half 0..15
    const int ub  = hb * 16 + ubh;       // global batch row 0..31
    const int uq  = (u & 7) * 4;         // units uq..uq+3

    // ---- Preload weights into SMEM: W[lay][row][kh*36 + k'] ----
    for (int idx = tid; idx < 4096; idx += NTHREADS) {
        int row = idx >> 5, k = idx & 31;
        smem[OFF_W + row * WST + k]             = Wih0[idx];
        smem[OFF_W + row * WST + 36 + k]        = Whh0[idx];
        smem[OFF_W + WLAY + row * WST + k]      = Wih1[idx];
        smem[OFF_W + WLAY + row * WST + 36 + k] = Whh1[idx];
    }
    if (tid < 128) {
        smem[OFF_B0 + tid] = bih0[tid] + bhh0[tid];
        smem[OFF_B1 + tid] = bih1[tid] + bhh1[tid];
    }
    if (tid < 32) { smem[OFF_W1S + tid] = w1[tid]; smem[OFF_B1S + tid] = b1[tid]; }
    if (tid < 64) { smem[OFF_W2S + tid] = w2[tid]; }
    for (int idx = tid; idx < 3 * 32 * IST; idx += NTHREADS) in0[idx] = 0.f;
    __syncthreads();

    // per-thread invariants
    const float* biasL = smem + (lay ? OFF_B1 : OFF_B0);
    float4 bzi = *(const float4*)(biasL + 0  + uq);
    float4 bzf = *(const float4*)(biasL + 32 + uq);
    float4 bzg = *(const float4*)(biasL + 64 + uq);
    float4 bzo = *(const float4*)(biasL + 96 + uq);
    const float* Wb = smem + OFF_W + lay * WLAY + kh * 36;
    float* gsg = smem + OFF_GS + gid * GSG;          // this group's gs base
    float* gsb = gsg + kh * GSK;                     // this thread's store plane
    const float* gu0 = gsg + ubh * GSB + uq;
    const float* gu1 = gu0 + GSK;
    const int ibar = 1 + gid;                        // group-internal barrier
    const int rbar = 5 + hb;                         // h0 ready (L0 arrive, L1 sync)
    const int fbar = 7 + hb;                         // buffer free (L1 arrive, L0 sync)
    const int hrow0 = hb * 16 * IST;                 // half base row offset

    if (lay == 0) {
        float4 w1v = *(const float4*)(smem + OFF_W1S + uq);
        float4 b1v = *(const float4*)(smem + OFF_B1S + uq);
        const float* __restrict__ seq = tensor + (long)(blockIdx.x * 32 + ub) * TSTEPS;
        const float* inb = in0 + hrow0 + kh * 36;

        {   // x(0) (h-half already zero)
            float s = seq[0];
            float4 x;
            x.x = fmaxf(fmaf(s, w1v.x, b1v.x), 0.f);
            x.y = fmaxf(fmaf(s, w1v.y, b1v.y), 0.f);
            x.z = fmaxf(fmaf(s, w1v.z, b1v.z), 0.f);
            x.w = fmaxf(fmaf(s, w1v.w, b1v.w), 0.f);
            *(float4*)&in0[ub * IST + uq] = x;
        }
        float c0 = 0.f, c1 = 0.f, c2 = 0.f, c3 = 0.f;
        bar_sync(ibar, 128);                          // in0 init visible in group

        for (int t = 0; t < TSTEPS; t++) {
            gate_phase(Wb, inb, gsb, rg, bq);         // gs0(t)
            bar_sync(ibar, 128);                      // gs ready

            float4 h = do_update(gu0, gu1, bzi, bzf, bzg, bzo, c0, c1, c2, c3);
            *(float4*)&in0[ub * IST + 36 + uq] = h;   // h0 -> next L0 input
            float* bx = (t & 1) ? in1b : in1a;
            bar_sync(fbar, 256);                      // buffer free (slack-1)
            *(float4*)&bx[ub * IST + uq] = h;         // h0 -> L1 input buffer
            bar_arrive(rbar, 256);                    // publish h0(t)
            if (t + 1 < TSTEPS) {
                float s = seq[t + 1];
                float4 x;
                x.x = fmaxf(fmaf(s, w1v.x, b1v.x), 0.f);
                x.y = fmaxf(fmaf(s, w1v.y, b1v.y), 0.f);
                x.z = fmaxf(fmaf(s, w1v.z, b1v.z), 0.f);
                x.w = fmaxf(fmaf(s, w1v.w, b1v.w), 0.f);
                *(float4*)&in0[ub * IST + uq] = x;    // x(t+1)
            }
            bar_sync(ibar, 128);                      // in0 ready, gs free
        }
    } else {
        float c0 = 0.f, c1 = 0.f, c2 = 0.f, c3 = 0.f;
        bar_arrive(fbar, 256);                        // prime backpressure

        for (int t = 0; t < TSTEPS; t++) {
            bar_sync(rbar, 256);                      // h0(t) ready in buf t&1
            const float* inb = ((t & 1) ? in1b : in1a) + hrow0 + kh * 36;
            gate_phase(Wb, inb, gsb, rg, bq);         // gs1(t)
            bar_arrive(fbar, 256);                    // done reading buf t&1
            bar_sync(ibar, 128);                      // gs ready

            float4 h = do_update(gu0, gu1, bzi, bzf, bzg, bzo, c0, c1, c2, c3);
            *(float4*)&in1a[ub * IST + 36 + uq] = h;  // h1 -> both buffers
            *(float4*)&in1b[ub * IST + 36 + uq] = h;
            bar_sync(ibar, 128);                      // h1 ready, gs free
        }
    }

    __syncthreads();

    // ---- Head: out[b] = [h0_final ; h1_final] . w2 + b2 ----
    // final t = 511 (odd) -> in1b: x-half = h0(T-1), h-half = h1(T-1)
    if (tid < 32) {
        const float* hbp = in1b + tid * IST;
        const float* w2s = smem + OFF_W2S;
        float acc = 0.f;
#pragma unroll
        for (int k = 0; k < 32; k++) acc = fmaf(w2s[k], hbp[k], acc);
#pragma unroll
        for (int k = 0; k < 32; k++) acc = fmaf(w2s[32 + k], hbp[36 + k], acc);
        out[blockIdx.x * 32 + tid] = acc + b2[0];
    }
}

extern "C" void kernel_launch(void* const* d_in, const int* in_sizes, int n_in,
                              void* d_out, int out_size) {
    const float* tensor = (const float*)d_in[0];
    const float* w1     = (const float*)d_in[1];
    const float* b1     = (const float*)d_in[2];
    const float* Wih0   = (const float*)d_in[3];
    const float* Whh0   = (const float*)d_in[4];
    const float* bih0   = (const float*)d_in[5];
    const float* bhh0   = (const float*)d_in[6];
    const float* Wih1   = (const float*)d_in[7];
    const float* Whh1   = (const float*)d_in[8];
    const float* bih1   = (const float*)d_in[9];
    const float* bhh1   = (const float*)d_in[10];
    const float* w2     = (const float*)d_in[11];
    const float* b2     = (const float*)d_in[12];
    float* out = (float*)d_out;

    int Btot = in_sizes[0] / TSTEPS;   // 4096
    int grid = (Btot + 31) / 32;       // 128 CTAs

    cudaFuncSetAttribute(lstm_fused_kernel,
                         cudaFuncAttributeMaxDynamicSharedMemorySize, SMEM_BYTES);
    lstm_fused_kernel<<<grid, NTHREADS, SMEM_BYTES>>>(
        tensor, w1, b1, Wih0, Whh0, bih0, bhh0,
        Wih1, Whh1, bih1, bhh1, w2, b2, out);
}

// round 13
// speedup vs baseline: 1.1361x; 1.1361x over previous
#include <cuda_runtime.h>

#define TSTEPS   512
#define NTHREADS 512

// SMEM geometry (floats)
#define WST  76          // weight row stride: k' 0..31 at kh*36, pad to 76
#define IST  72          // input row per batch: kh*36 + k' (x|h), pad to 72
#define GSB  132         // gs per-batch stride: 128 gates + 4
#define GSK  4240        // gs kh-plane stride: 32*132 + 16
#define GSL  (2*GSK)     // gs per-layer: 8480

#define OFF_W    0           // 2 * 128*76 = 19456
#define WLAY     (128*WST)   // 9728
#define OFF_GS   19456       // 2 * 8480 = 16960
#define OFF_IN0  36416       // 32*72  L0 input [x | h0]
#define OFF_I1A  38720       // 32*72  L1 input buffer A [h0 | h1]
#define OFF_I1B  41024       // 32*72  L1 input buffer B [h0 | h1]
#define OFF_B0   43328       // 128
#define OFF_B1   43456       // 128
#define OFF_W1S  43584       // 32
#define OFF_B1S  43616       // 32
#define OFF_W2S  43648       // 64
#define SMEM_FLOATS 43712
#define SMEM_BYTES  (SMEM_FLOATS * 4)   // 174848

typedef unsigned long long ull;

#define BARS(id, cnt) asm volatile("bar.sync "   #id ", " #cnt ";" ::: "memory")
#define BARA(id, cnt) asm volatile("bar.arrive " #id ", " #cnt ";" ::: "memory")

__device__ __forceinline__ float sum2(ull v) {
    float lo, hi;
    asm("mov.b64 {%0,%1}, %2;" : "=f"(lo), "=f"(hi) : "l"(v));
    return lo + hi;
}
__device__ __forceinline__ void ffma2(ull& d, ull a, ull b) {
    asm("fma.rn.f32x2 %0, %1, %2, %0;" : "+l"(d) : "l"(a), "l"(b));
}
// MUFU tanh (sm_75+): 1 instruction, lat ~16
__device__ __forceinline__ float tanh_(float v) {
    float r;
    asm("tanh.approx.f32 %0, %1;" : "=f"(r) : "f"(v));
    return r;
}
// sigmoid(v) = 0.5*tanh(0.5*v) + 0.5  -> 1 MUFU + 2 FMA
__device__ __forceinline__ float sigm(float v) {
    float r;
    asm("tanh.approx.f32 %0, %1;" : "=f"(r) : "f"(0.5f * v));
    return fmaf(0.5f, r, 0.5f);
}

// Gate partial-GEMM: thread computes 8 rows (rg*8..+7) x 4 batches (bq+8i)
// over one 32-k half (kh). Bytes/MAC = 1.5. (Verified conflict-free in R10.)
__device__ __forceinline__ void gate_phase(const float* __restrict__ Wb,
                                           const float* __restrict__ inb,
                                           float* __restrict__ gsb,
                                           int rg, int bq) {
    ull acc[8][4];
#pragma unroll
    for (int j = 0; j < 8; j++)
#pragma unroll
        for (int i = 0; i < 4; i++) acc[j][i] = 0ull;

    const float* wr = Wb + rg * 8 * WST;
#pragma unroll
    for (int kq = 0; kq < 8; kq++) {
        ulonglong2 in[4];
#pragma unroll
        for (int i = 0; i < 4; i++)
            in[i] = *(const ulonglong2*)(inb + (bq + 8 * i) * IST + kq * 4);
#pragma unroll
        for (int j = 0; j < 8; j++) {
            ulonglong2 w = *(const ulonglong2*)(wr + j * WST + kq * 4);
#pragma unroll
            for (int i = 0; i < 4; i++) {
                ffma2(acc[j][i], w.x, in[i].x);
                ffma2(acc[j][i], w.y, in[i].y);
            }
        }
    }
#pragma unroll
    for (int i = 0; i < 4; i++) {
        float4 v0, v1;
        v0.x = sum2(acc[0][i]); v0.y = sum2(acc[1][i]);
        v0.z = sum2(acc[2][i]); v0.w = sum2(acc[3][i]);
        v1.x = sum2(acc[4][i]); v1.y = sum2(acc[5][i]);
        v1.z = sum2(acc[6][i]); v1.w = sum2(acc[7][i]);
        float* p = gsb + (bq + 8 * i) * GSB + rg * 8;
        *(float4*)p       = v0;
        *(float4*)(p + 4) = v1;
    }
}

// Gate partials (2 k-halves) -> activations -> c/h update for 4 units.
__device__ __forceinline__ float4 do_update(const float* gu0, const float* gu1,
                                            float4 bzi, float4 bzf, float4 bzg, float4 bzo,
                                            float& c0, float& c1, float& c2, float& c3) {
    float4 pi0 = *(const float4*)(gu0 + 0),  pi1 = *(const float4*)(gu1 + 0);
    float4 pf0 = *(const float4*)(gu0 + 32), pf1 = *(const float4*)(gu1 + 32);
    float4 pg0 = *(const float4*)(gu0 + 64), pg1 = *(const float4*)(gu1 + 64);
    float4 po0 = *(const float4*)(gu0 + 96), po1 = *(const float4*)(gu1 + 96);
    float iv0 = sigm(pi0.x + pi1.x + bzi.x), iv1 = sigm(pi0.y + pi1.y + bzi.y);
    float iv2 = sigm(pi0.z + pi1.z + bzi.z), iv3 = sigm(pi0.w + pi1.w + bzi.w);
    float fv0 = sigm(pf0.x + pf1.x + bzf.x), fv1 = sigm(pf0.y + pf1.y + bzf.y);
    float fv2 = sigm(pf0.z + pf1.z + bzf.z), fv3 = sigm(pf0.w + pf1.w + bzf.w);
    float gv0 = tanh_(pg0.x + pg1.x + bzg.x), gv1 = tanh_(pg0.y + pg1.y + bzg.y);
    float gv2 = tanh_(pg0.z + pg1.z + bzg.z), gv3 = tanh_(pg0.w + pg1.w + bzg.w);
    float ov0 = sigm(po0.x + po1.x + bzo.x), ov1 = sigm(po0.y + po1.y + bzo.y);
    float ov2 = sigm(po0.z + po1.z + bzo.z), ov3 = sigm(po0.w + po1.w + bzo.w);
    c0 = fmaf(fv0, c0, iv0 * gv0);
    c1 = fmaf(fv1, c1, iv1 * gv1);
    c2 = fmaf(fv2, c2, iv2 * gv2);
    c3 = fmaf(fv3, c3, iv3 * gv3);
    float4 h;
    h.x = ov0 * tanh_(c0);
    h.y = ov1 * tanh_(c1);
    h.z = ov2 * tanh_(c2);
    h.w = ov3 * tanh_(c3);
    return h;
}

__global__ void __launch_bounds__(NTHREADS, 1)
lstm_fused_kernel(const float* __restrict__ tensor,
                  const float* __restrict__ w1,   const float* __restrict__ b1,
                  const float* __restrict__ Wih0, const float* __restrict__ Whh0,
                  const float* __restrict__ bih0, const float* __restrict__ bhh0,
                  const float* __restrict__ Wih1, const float* __restrict__ Whh1,
                  const float* __restrict__ bih1, const float* __restrict__ bhh1,
                  const float* __restrict__ w2,   const float* __restrict__ b2,
                  float* __restrict__ out) {
    extern __shared__ float smem[];
    float* in0  = smem + OFF_IN0;
    float* in1a = smem + OFF_I1A;
    float* in1b = smem + OFF_I1B;

    const int tid = threadIdx.x;
    const int lay = tid >> 8;           // warps 0-7: layer0, 8-15: layer1
    const int u   = tid & 255;
    const int kh = u & 1;
    const int bq = (u >> 1) & 7;
    const int rg = u >> 4;
    const int ub = u >> 3;              // update: batch 0..31
    const int uq = (u & 7) * 4;         // update: units uq..uq+3

    // ---- Preload weights into SMEM: W[lay][row][kh*36 + k'] ----
    for (int idx = tid; idx < 4096; idx += NTHREADS) {
        int row = idx >> 5, k = idx & 31;
        smem[OFF_W + row * WST + k]             = Wih0[idx];
        smem[OFF_W + row * WST + 36 + k]        = Whh0[idx];
        smem[OFF_W + WLAY + row * WST + k]      = Wih1[idx];
        smem[OFF_W + WLAY + row * WST + 36 + k] = Whh1[idx];
    }
    if (tid < 128) {
        smem[OFF_B0 + tid] = bih0[tid] + bhh0[tid];
        smem[OFF_B1 + tid] = bih1[tid] + bhh1[tid];
    }
    if (tid < 32) { smem[OFF_W1S + tid] = w1[tid]; smem[OFF_B1S + tid] = b1[tid]; }
    if (tid < 64) { smem[OFF_W2S + tid] = w2[tid]; }
    // zero all input staging (x & h slots of in0, in1a, in1b)
    for (int idx = tid; idx < 3 * 32 * IST; idx += NTHREADS) in0[idx] = 0.f;
    __syncthreads();

    // per-thread invariants
    const float* biasL = smem + (lay ? OFF_B1 : OFF_B0);
    float4 bzi = *(const float4*)(biasL + 0  + uq);
    float4 bzf = *(const float4*)(biasL + 32 + uq);
    float4 bzg = *(const float4*)(biasL + 64 + uq);
    float4 bzo = *(const float4*)(biasL + 96 + uq);
    const float* Wb = smem + OFF_W + lay * WLAY + kh * 36;
    float* gsb = smem + OFF_GS + lay * GSL + kh * GSK;
    const float* gu0 = smem + OFF_GS + lay * GSL + ub * GSB + uq;
    const float* gu1 = gu0 + GSK;

    if (lay == 0) {
        float4 w1v = *(const float4*)(smem + OFF_W1S + uq);
        float4 b1v = *(const float4*)(smem + OFF_B1S + uq);
        const float* __restrict__ seq = tensor + (long)(blockIdx.x * 32 + ub) * TSTEPS;
        const float* inb = in0 + kh * 36;

        // x(0) into in0 (h-half already zero)
        {
            float s = seq[0];
            float4 x;
            x.x = fmaxf(fmaf(s, w1v.x, b1v.x), 0.f);
            x.y = fmaxf(fmaf(s, w1v.y, b1v.y), 0.f);
            x.z = fmaxf(fmaf(s, w1v.z, b1v.z), 0.f);
            x.w = fmaxf(fmaf(s, w1v.w, b1v.w), 0.f);
            *(float4*)&in0[ub * IST + uq] = x;
        }
        float c0 = 0.f, c1 = 0.f, c2 = 0.f, c3 = 0.f;
        BARS(1, 256);                                   // in0 init visible to group

        for (int t = 0; t < TSTEPS; t++) {
            gate_phase(Wb, inb, gsb, rg, bq);           // gs0(t)
            BARS(1, 256);                               // gs0 ready

            float4 h = do_update(gu0, gu1, bzi, bzf, bzg, bzo, c0, c1, c2, c3);
            *(float4*)&in0[ub * IST + 36 + uq] = h;     // h0 -> next L0 input
            float* bx = (t & 1) ? in1b : in1a;
            BARS(4, 512);                               // backpressure (slack-1)
            *(float4*)&bx[ub * IST + uq] = h;           // h0 -> L1 input buffer
            BARA(3, 512);                               // h0(t) published
            if (t + 1 < TSTEPS) {
                float s = seq[t + 1];
                float4 x;
                x.x = fmaxf(fmaf(s, w1v.x, b1v.x), 0.f);
                x.y = fmaxf(fmaf(s, w1v.y, b1v.y), 0.f);
                x.z = fmaxf(fmaf(s, w1v.z, b1v.z), 0.f);
                x.w = fmaxf(fmaf(s, w1v.w, b1v.w), 0.f);
                *(float4*)&in0[ub * IST + uq] = x;      // x(t+1)
            }
            BARS(1, 256);                               // in0 ready, gs0 free
        }
    } else {
        float c0 = 0.f, c1 = 0.f, c2 = 0.f, c3 = 0.f;
        BARA(4, 512);                                   // prime backpressure (1 round)

        for (int t = 0; t < TSTEPS; t++) {
            BARS(3, 512);                               // h0(t) available in buf t&1
            const float* inb = ((t & 1) ? in1b : in1a) + kh * 36;
            gate_phase(Wb, inb, gsb, rg, bq);           // gs1(t)
            BARA(4, 512);                               // done reading buf t&1
            BARS(2, 256);                               // gs1 ready

            float4 h = do_update(gu0, gu1, bzi, bzf, bzg, bzo, c0, c1, c2, c3);
            *(float4*)&in1a[ub * IST + 36 + uq] = h;    // h1 -> both buffers' h-half
            *(float4*)&in1b[ub * IST + 36 + uq] = h;
            BARS(2, 256);                               // h1 ready, gs1 free
        }
    }

    __syncthreads();

    // ---- Head: out[b] = [h0_final ; h1_final] . w2 + b2 ----
    // final t = 511 (odd) -> in1b: x-half = h0(T-1), h-half = h1(T-1)
    if (tid < 32) {
        const float* hb  = in1b + tid * IST;
        const float* w2s = smem + OFF_W2S;
        float acc = 0.f;
#pragma unroll
        for (int k = 0; k < 32; k++) acc = fmaf(w2s[k], hb[k], acc);
#pragma unroll
        for (int k = 0; k < 32; k++) acc = fmaf(w2s[32 + k], hb[36 + k], acc);
        out[blockIdx.x * 32 + tid] = acc + b2[0];
    }
}

extern "C" void kernel_launch(void* const* d_in, const int* in_sizes, int n_in,
                              void* d_out, int out_size) {
    const float* tensor = (const float*)d_in[0];
    const float* w1     = (const float*)d_in[1];
    const float* b1     = (const float*)d_in[2];
    const float* Wih0   = (const float*)d_in[3];
    const float* Whh0   = (const float*)d_in[4];
    const float* bih0   = (const float*)d_in[5];
    const float* bhh0   = (const float*)d_in[6];
    const float* Wih1   = (const float*)d_in[7];
    const float* Whh1   = (const float*)d_in[8];
    const float* bih1   = (const float*)d_in[9];
    const float* bhh1   = (const float*)d_in[10];
    const float* w2     = (const float*)d_in[11];
    const float* b2     = (const float*)d_in[12];
    float* out = (float*)d_out;

    int Btot = in_sizes[0] / TSTEPS;   // 4096
    int grid = (Btot + 31) / 32;       // 128 CTAs

    cudaFuncSetAttribute(lstm_fused_kernel,
                         cudaFuncAttributeMaxDynamicSharedMemorySize, SMEM_BYTES);
    lstm_fused_kernel<<<grid, NTHREADS, SMEM_BYTES>>>(
        tensor, w1, b1, Wih0, Whh0, bih0, bhh0,
        Wih1, Whh1, bih1, bhh1, w2, b2, out);
}

// round 15
// speedup vs baseline: 1.1700x; 1.0298x over previous
#include <cuda_runtime.h>

#define TSTEPS   512
#define NTHREADS 512

// SMEM geometry (floats)
#define WST 72           // weight row: k' 0..31 at kh*36; 8 pad (bank-verified)
#define IST 76           // input row per batch: [x/h0 at 0..31 | h at 36..67]
#define WLAY (128*WST)

#define OFF_W    0                      // 2 * 128*72 = 18432
#define OFF_I0A  18432                  // 32*76 = 2432 each
#define OFF_I0B  (OFF_I0A + 32*IST)
#define OFF_I1A  (OFF_I0B + 32*IST)
#define OFF_I1B  (OFF_I1A + 32*IST)
#define OFF_B0   (OFF_I1B + 32*IST)     // 128
#define OFF_B1   (OFF_B0 + 128)
#define OFF_W1S  (OFF_B1 + 128)         // 32
#define OFF_B1S  (OFF_W1S + 32)         // 32
#define OFF_W2S  (OFF_B1S + 32)         // 64
#define SMEM_FLOATS (OFF_W2S + 64)
#define SMEM_BYTES  (SMEM_FLOATS * 4)   // ~114 KB

typedef unsigned long long ull;

#define BARS(id, cnt) asm volatile("bar.sync "   #id ", " #cnt ";" ::: "memory")
#define BARA(id, cnt) asm volatile("bar.arrive " #id ", " #cnt ";" ::: "memory")

__device__ __forceinline__ float sum2(ull v) {
    float lo, hi;
    asm("mov.b64 {%0,%1}, %2;" : "=f"(lo), "=f"(hi) : "l"(v));
    return lo + hi;
}
__device__ __forceinline__ void ffma2(ull& d, ull a, ull b) {
    asm("fma.rn.f32x2 %0, %1, %2, %0;" : "+l"(d) : "l"(a), "l"(b));
}
__device__ __forceinline__ float tanh_(float v) {
    float r;
    asm("tanh.approx.f32 %0, %1;" : "=f"(r) : "f"(v));
    return r;
}
__device__ __forceinline__ float sigm(float v) {
    float r;
    asm("tanh.approx.f32 %0, %1;" : "=f"(r) : "f"(0.5f * v));
    return fmaf(0.5f, r, 0.5f);
}

// Gate GEMM tile: rows {j, j+32, j+64, j+96} x 8 batches (bg*8..+7) over one
// 32-k half (kh). Wj = weight base for row j incl. lay & kh offsets.
// inb = input buffer + kh*36 (kh0 = x/h0 region, kh1 = recurrent h region).
__device__ __forceinline__ void gemm_tile(const float* __restrict__ Wj,
                                          const float* __restrict__ inb,
                                          int bg, ull acc[4][8]) {
#pragma unroll
    for (int kq = 0; kq < 8; kq++) {
        ulonglong2 in[8];
#pragma unroll
        for (int ib = 0; ib < 8; ib++)
            in[ib] = *(const ulonglong2*)(inb + (bg * 8 + ib) * IST + kq * 4);
#pragma unroll
        for (int r = 0; r < 4; r++) {
            ulonglong2 w = *(const ulonglong2*)(Wj + r * 32 * WST + kq * 4);
#pragma unroll
            for (int ib = 0; ib < 8; ib++) {
                ffma2(acc[r][ib], w.x, in[ib].x);
                ffma2(acc[r][ib], w.y, in[ib].y);
            }
        }
    }
}

// kh-pair merge (shfl.bfly 1) + activations + c/h update for 4 batches.
__device__ __forceinline__ void merge_update(ull acc[4][8], int kh,
                                             float bzi, float bzf, float bzg, float bzo,
                                             float* c, float* h) {
    float R[4][4];
#pragma unroll
    for (int r = 0; r < 4; r++)
#pragma unroll
        for (int i = 0; i < 4; i++) {
            float keep = kh ? sum2(acc[r][4 + i]) : sum2(acc[r][i]);
            float send = kh ? sum2(acc[r][i])     : sum2(acc[r][4 + i]);
            R[r][i] = keep + __shfl_xor_sync(0xffffffffu, send, 1);
        }
#pragma unroll
    for (int i = 0; i < 4; i++) {
        float iv = sigm(R[0][i] + bzi);
        float fv = sigm(R[1][i] + bzf);
        float gv = tanh_(R[2][i] + bzg);
        float ov = sigm(R[3][i] + bzo);
        c[i] = fmaf(fv, c[i], iv * gv);
        h[i] = ov * tanh_(c[i]);
    }
}

__global__ void __launch_bounds__(NTHREADS, 1)
lstm_fused_kernel(const float* __restrict__ tensor,
                  const float* __restrict__ w1,   const float* __restrict__ b1,
                  const float* __restrict__ Wih0, const float* __restrict__ Whh0,
                  const float* __restrict__ bih0, const float* __restrict__ bhh0,
                  const float* __restrict__ Wih1, const float* __restrict__ Whh1,
                  const float* __restrict__ bih1, const float* __restrict__ bhh1,
                  const float* __restrict__ w2,   const float* __restrict__ b2,
                  float* __restrict__ out) {
    extern __shared__ float smem[];
    float* i0a = smem + OFF_I0A;
    float* i0b = smem + OFF_I0B;
    float* i1a = smem + OFF_I1A;
    float* i1b = smem + OFF_I1B;

    const int tid = threadIdx.x;
    const int lay = tid >> 8;                 // 256 threads per layer group
    const int u   = tid & 255;
    // lane bits: 0=kh, 1-3=j0..2, 4=j3 ; warp bits: 5-6=bg, 7=j4
    const int kh = u & 1;
    const int j  = ((u >> 1) & 7) | (((u >> 4) & 1) << 3) | (((u >> 7) & 1) << 4);
    const int bg = (u >> 5) & 3;
    const int bm = bg * 8 + kh * 4;           // this thread's 4 batches: bm..bm+3

    // ---- Preload weights: row r at [lay][r*WST + kh*36 + k'] ----
    for (int idx = tid; idx < 4096; idx += NTHREADS) {
        int row = idx >> 5, k = idx & 31;
        smem[OFF_W + row * WST + k]             = Wih0[idx];
        smem[OFF_W + row * WST + 36 + k]        = Whh0[idx];
        smem[OFF_W + WLAY + row * WST + k]      = Wih1[idx];
        smem[OFF_W + WLAY + row * WST + 36 + k] = Whh1[idx];
    }
    if (tid < 128) {
        smem[OFF_B0 + tid] = bih0[tid] + bhh0[tid];
        smem[OFF_B1 + tid] = bih1[tid] + bhh1[tid];
    }
    if (tid < 32) { smem[OFF_W1S + tid] = w1[tid]; smem[OFF_B1S + tid] = b1[tid]; }
    if (tid < 64) { smem[OFF_W2S + tid] = w2[tid]; }
    // zero all 4 input staging buffers (contiguous)
    for (int idx = tid; idx < 4 * 32 * IST; idx += NTHREADS) i0a[idx] = 0.f;
    __syncthreads();

    // prime x(0) into i0a x-region
    for (int idx = tid; idx < 1024; idx += NTHREADS) {
        int b = idx >> 5, jj = idx & 31;
        float s = tensor[(long)(blockIdx.x * 32 + b) * TSTEPS];
        i0a[b * IST + jj] = fmaxf(fmaf(s, smem[OFF_W1S + jj], smem[OFF_B1S + jj]), 0.f);
    }

    // per-thread invariants
    const float* biasL = smem + (lay ? OFF_B1 : OFF_B0);
    const float bzi = biasL[j],      bzf = biasL[32 + j];
    const float bzg = biasL[64 + j], bzo = biasL[96 + j];
    const float* Wj = smem + OFF_W + lay * WLAY + j * WST + kh * 36;
    const float w1j = smem[OFF_W1S + j], b1j = smem[OFF_B1S + j];
    const float* __restrict__ seqb = tensor + (long)(blockIdx.x * 32 + bm) * TSTEPS;
    float c[4] = {0.f, 0.f, 0.f, 0.f};
    float h[4];
    __syncthreads();

    if (lay == 0) {
        for (int t = 0; t < TSTEPS; t++) {
            const float* cur = (t & 1) ? i0b : i0a;
            float*       nxt = (t & 1) ? i0a : i0b;
            ull acc[4][8];
#pragma unroll
            for (int r = 0; r < 4; r++)
#pragma unroll
                for (int ib = 0; ib < 8; ib++) acc[r][ib] = 0ull;
            gemm_tile(Wj, cur + kh * 36, bg, acc);
            merge_update(acc, kh, bzi, bzf, bzg, bzo, c, h);

            // h0 -> next L0 input (h-region) + x(t+1) (x-region)
#pragma unroll
            for (int i = 0; i < 4; i++) nxt[(bm + i) * IST + 36 + j] = h[i];
            if (t + 1 < TSTEPS) {
#pragma unroll
                for (int i = 0; i < 4; i++) {
                    float s = seqb[i * TSTEPS + t + 1];
                    nxt[(bm + i) * IST + j] = fmaxf(fmaf(s, w1j, b1j), 0.f);
                }
            }
            BARS(4, 512);                             // L1 done reading in1[t&1]
            float* cb = (t & 1) ? i1b : i1a;
#pragma unroll
            for (int i = 0; i < 4; i++) cb[(bm + i) * IST + j] = h[i];  // h0 -> L1
            BARA(3, 512);                             // publish h0(t)
            BARS(1, 256);                             // group: nxt complete
        }
    } else {
        BARA(4, 512);                                 // prime backpressure
        for (int t = 0; t < TSTEPS; t++) {
            BARS(3, 512);                             // h0(t) ready in in1[t&1]
            const float* cur = (t & 1) ? i1b : i1a;
            float*       nxt = (t & 1) ? i1a : i1b;
            ull acc[4][8];
#pragma unroll
            for (int r = 0; r < 4; r++)
#pragma unroll
                for (int ib = 0; ib < 8; ib++) acc[r][ib] = 0ull;
            gemm_tile(Wj, cur + kh * 36, bg, acc);
            BARA(4, 512);                             // done reading in1[t&1]
            merge_update(acc, kh, bzi, bzf, bzg, bzo, c, h);
#pragma unroll
            for (int i = 0; i < 4; i++) nxt[(bm + i) * IST + 36 + j] = h[i];  // h1
            BARS(2, 256);                             // group: h1 complete
        }
    }

    __syncthreads();

    // ---- Head: final t=511 (odd): h0(511) in i1b x-region, h1(511) in i1a h-region
    if (tid < 32) {
        const float* w2s = smem + OFF_W2S;
        float acc = 0.f;
#pragma unroll
        for (int k = 0; k < 32; k++) acc = fmaf(w2s[k],      i1b[tid * IST + k],      acc);
#pragma unroll
        for (int k = 0; k < 32; k++) acc = fmaf(w2s[32 + k], i1a[tid * IST + 36 + k], acc);
        out[blockIdx.x * 32 + tid] = acc + b2[0];
    }
}

extern "C" void kernel_launch(void* const* d_in, const int* in_sizes, int n_in,
                              void* d_out, int out_size) {
    const float* tensor = (const float*)d_in[0];
    const float* w1     = (const float*)d_in[1];
    const float* b1     = (const float*)d_in[2];
    const float* Wih0   = (const float*)d_in[3];
    const float* Whh0   = (const float*)d_in[4];
    const float* bih0   = (const float*)d_in[5];
    const float* bhh0   = (const float*)d_in[6];
    const float* Wih1   = (const float*)d_in[7];
    const float* Whh1   = (const float*)d_in[8];
    const float* bih1   = (const float*)d_in[9];
    const float* bhh1   = (const float*)d_in[10];
    const float* w2     = (const float*)d_in[11];
    const float* b2     = (const float*)d_in[12];
    float* out = (float*)d_out;

    int Btot = in_sizes[0] / TSTEPS;   // 4096
    int grid = (Btot + 31) / 32;       // 128 CTAs

    cudaFuncSetAttribute(lstm_fused_kernel,
                         cudaFuncAttributeMaxDynamicSharedMemorySize, SMEM_BYTES);
    lstm_fused_kernel<<<grid, NTHREADS, SMEM_BYTES>>>(
        tensor, w1, b1, Wih0, Whh0, bih0, bhh0,
        Wih1, Whh1, bih1, bhh1, w2, b2, out);
}

// round 17
// speedup vs baseline: 1.3126x; 1.1219x over previous
#include <cuda_runtime.h>

#define TSTEPS   512
#define NTHREADS 512
#define NB       28      // batch tile per CTA (grid 147 ~= 148 SMs)
#define BTOT     4096

// SMEM geometry (floats)
#define WST 72           // weight row: k' 0..31 at kh*36; 8 pad (bank-verified)
#define IST 76           // input row per batch: [x/h0 at 0..31 | h at 36..67]
#define WLAY (128*WST)

#define OFF_W    0                      // 2 * 128*72 = 18432
#define OFF_I0A  18432                  // 32*76 rows allocated (28 used)
#define OFF_I0B  (OFF_I0A + 32*IST)
#define OFF_I1A  (OFF_I0B + 32*IST)
#define OFF_I1B  (OFF_I1A + 32*IST)
#define OFF_B0   (OFF_I1B + 32*IST)     // 128
#define OFF_B1   (OFF_B0 + 128)
#define OFF_W1S  (OFF_B1 + 128)         // 32
#define OFF_B1S  (OFF_W1S + 32)         // 32
#define OFF_W2S  (OFF_B1S + 32)         // 64
#define SMEM_FLOATS (OFF_W2S + 64)
#define SMEM_BYTES  (SMEM_FLOATS * 4)

typedef unsigned long long ull;

#define BARS(id, cnt) asm volatile("bar.sync "   #id ", " #cnt ";" ::: "memory")
#define BARA(id, cnt) asm volatile("bar.arrive " #id ", " #cnt ";" ::: "memory")

__device__ __forceinline__ float sum2(ull v) {
    float lo, hi;
    asm("mov.b64 {%0,%1}, %2;" : "=f"(lo), "=f"(hi) : "l"(v));
    return lo + hi;
}
__device__ __forceinline__ void ffma2(ull& d, ull a, ull b) {
    asm("fma.rn.f32x2 %0, %1, %2, %0;" : "+l"(d) : "l"(a), "l"(b));
}
__device__ __forceinline__ float tanh_(float v) {
    float r;
    asm("tanh.approx.f32 %0, %1;" : "=f"(r) : "f"(v));
    return r;
}
__device__ __forceinline__ float sigm(float v) {
    float r;
    asm("tanh.approx.f32 %0, %1;" : "=f"(r) : "f"(0.5f * v));
    return fmaf(0.5f, r, 0.5f);
}

// Gate GEMM tile: rows {j, j+32, j+64, j+96} x 7 batches (bg*7..+6) over one
// 32-k half (kh). Wj = weight base for row j incl. lay & kh offsets.
__device__ __forceinline__ void gemm_tile(const float* __restrict__ Wj,
                                          const float* __restrict__ inb,
                                          int bg, ull acc[4][7]) {
#pragma unroll
    for (int kq = 0; kq < 8; kq++) {
        ulonglong2 in[7];
#pragma unroll
        for (int ib = 0; ib < 7; ib++)
            in[ib] = *(const ulonglong2*)(inb + (bg * 7 + ib) * IST + kq * 4);
#pragma unroll
        for (int r = 0; r < 4; r++) {
            ulonglong2 w = *(const ulonglong2*)(Wj + r * 32 * WST + kq * 4);
#pragma unroll
            for (int ib = 0; ib < 7; ib++) {
                ffma2(acc[r][ib], w.x, in[ib].x);
                ffma2(acc[r][ib], w.y, in[ib].y);
            }
        }
    }
}

// kh-pair merge (shfl.bfly 1) + activations + c/h update.
// kh0 thread keeps batches bg*7+0..3 (nb=4); kh1 keeps bg*7+4..6 (nb=3).
__device__ __forceinline__ void merge_update(ull acc[4][7], int kh,
                                             float bzi, float bzf, float bzg, float bzo,
                                             float* c, float* h) {
    float R[4][4];
#pragma unroll
    for (int r = 0; r < 4; r++)
#pragma unroll
        for (int i = 0; i < 4; i++) {
            float keep = kh ? ((i < 3) ? sum2(acc[r][4 + i]) : 0.f) : sum2(acc[r][i]);
            float send = kh ? sum2(acc[r][i]) : ((i < 3) ? sum2(acc[r][4 + i]) : 0.f);
            R[r][i] = keep + __shfl_xor_sync(0xffffffffu, send, 1);
        }
#pragma unroll
    for (int i = 0; i < 4; i++) {
        float iv = sigm(R[0][i] + bzi);
        float fv = sigm(R[1][i] + bzf);
        float gv = tanh_(R[2][i] + bzg);
        float ov = sigm(R[3][i] + bzo);
        c[i] = fmaf(fv, c[i], iv * gv);
        h[i] = ov * tanh_(c[i]);
    }
}

__global__ void __launch_bounds__(NTHREADS, 1)
lstm_fused_kernel(const float* __restrict__ tensor,
                  const float* __restrict__ w1,   const float* __restrict__ b1,
                  const float* __restrict__ Wih0, const float* __restrict__ Whh0,
                  const float* __restrict__ bih0, const float* __restrict__ bhh0,
                  const float* __restrict__ Wih1, const float* __restrict__ Whh1,
                  const float* __restrict__ bih1, const float* __restrict__ bhh1,
                  const float* __restrict__ w2,   const float* __restrict__ b2,
                  float* __restrict__ out) {
    extern __shared__ float smem[];
    float* i0a = smem + OFF_I0A;
    float* i0b = smem + OFF_I0B;
    float* i1a = smem + OFF_I1A;
    float* i1b = smem + OFF_I1B;

    const int tid = threadIdx.x;
    const int lay = tid >> 8;                 // 256 threads per layer group
    const int u   = tid & 255;
    // lane bits: 0=kh, 1-3=j0..2, 4=j3 ; warp bits: 5-6=bg, 7=j4
    const int kh = u & 1;
    const int j  = ((u >> 1) & 7) | (((u >> 4) & 1) << 3) | (((u >> 7) & 1) << 4);
    const int bg = (u >> 5) & 3;
    const int bm = bg * 7 + kh * 4;           // first owned batch
    const int nb = kh ? 3 : 4;                // owned batch count
    const int gb0 = blockIdx.x * NB;          // CTA's first global batch

    // ---- Preload weights: row r at [lay][r*WST + kh*36 + k'] ----
    for (int idx = tid; idx < 4096; idx += NTHREADS) {
        int row = idx >> 5, k = idx & 31;
        smem[OFF_W + row * WST + k]             = Wih0[idx];
        smem[OFF_W + row * WST + 36 + k]        = Whh0[idx];
        smem[OFF_W + WLAY + row * WST + k]      = Wih1[idx];
        smem[OFF_W + WLAY + row * WST + 36 + k] = Whh1[idx];
    }
    if (tid < 128) {
        smem[OFF_B0 + tid] = bih0[tid] + bhh0[tid];
        smem[OFF_B1 + tid] = bih1[tid] + bhh1[tid];
    }
    if (tid < 32) { smem[OFF_W1S + tid] = w1[tid]; smem[OFF_B1S + tid] = b1[tid]; }
    if (tid < 64) { smem[OFF_W2S + tid] = w2[tid]; }
    // zero all 4 input staging buffers (contiguous)
    for (int idx = tid; idx < 4 * 32 * IST; idx += NTHREADS) i0a[idx] = 0.f;
    __syncthreads();

    // prime x(0) into i0a x-region (clamped batch index for partial last CTA)
    for (int idx = tid; idx < NB * 32; idx += NTHREADS) {
        int b = idx >> 5, jj = idx & 31;
        int gb = gb0 + b; if (gb > BTOT - 1) gb = BTOT - 1;
        float s = tensor[(long)gb * TSTEPS];
        i0a[b * IST + jj] = fmaxf(fmaf(s, smem[OFF_W1S + jj], smem[OFF_B1S + jj]), 0.f);
    }

    // per-thread invariants
    const float* biasL = smem + (lay ? OFF_B1 : OFF_B0);
    const float bzi = biasL[j],      bzf = biasL[32 + j];
    const float bzg = biasL[64 + j], bzo = biasL[96 + j];
    const float* Wj = smem + OFF_W + lay * WLAY + j * WST + kh * 36;
    const float w1j = smem[OFF_W1S + j], b1j = smem[OFF_B1S + j];
    // clamped per-batch sequence bases (junk h for pad batches is harmless)
    long sbase[4];
#pragma unroll
    for (int i = 0; i < 4; i++) {
        int gb = gb0 + bm + i; if (gb > BTOT - 1) gb = BTOT - 1;
        sbase[i] = (long)gb * TSTEPS;
    }
    float c[4] = {0.f, 0.f, 0.f, 0.f};
    float h[4];
    __syncthreads();

    if (lay == 0) {
        for (int t = 0; t < TSTEPS; t++) {
            const float* cur = (t & 1) ? i0b : i0a;
            float*       nxt = (t & 1) ? i0a : i0b;
            ull acc[4][7];
#pragma unroll
            for (int r = 0; r < 4; r++)
#pragma unroll
                for (int ib = 0; ib < 7; ib++) acc[r][ib] = 0ull;
            gemm_tile(Wj, cur + kh * 36, bg, acc);
            merge_update(acc, kh, bzi, bzf, bzg, bzo, c, h);

            // h0 -> next L0 input (h-region) + x(t+1) (x-region)
#pragma unroll
            for (int i = 0; i < 4; i++)
                if (i < nb) nxt[(bm + i) * IST + 36 + j] = h[i];
            if (t + 1 < TSTEPS) {
#pragma unroll
                for (int i = 0; i < 4; i++)
                    if (i < nb) {
                        float s = tensor[sbase[i] + t + 1];
                        nxt[(bm + i) * IST + j] = fmaxf(fmaf(s, w1j, b1j), 0.f);
                    }
            }
            BARS(4, 512);                             // L1 done reading in1[t&1]
            float* cb = (t & 1) ? i1b : i1a;
#pragma unroll
            for (int i = 0; i < 4; i++)
                if (i < nb) cb[(bm + i) * IST + j] = h[i];   // h0 -> L1
            BARA(3, 512);                             // publish h0(t)
            BARS(1, 256);                             // group: nxt complete
        }
    } else {
        BARA(4, 512);                                 // prime backpressure
        for (int t = 0; t < TSTEPS; t++) {
            BARS(3, 512);                             // h0(t) ready in in1[t&1]
            const float* cur = (t & 1) ? i1b : i1a;
            float*       nxt = (t & 1) ? i1a : i1b;
            ull acc[4][7];
#pragma unroll
            for (int r = 0; r < 4; r++)
#pragma unroll
                for (int ib = 0; ib < 7; ib++) acc[r][ib] = 0ull;
            gemm_tile(Wj, cur + kh * 36, bg, acc);
            BARA(4, 512);                             // done reading in1[t&1]
            merge_update(acc, kh, bzi, bzf, bzg, bzo, c, h);
#pragma unroll
            for (int i = 0; i < 4; i++)
                if (i < nb) nxt[(bm + i) * IST + 36 + j] = h[i];  // h1
            BARS(2, 256);                             // group: h1 complete
        }
    }

    __syncthreads();

    // ---- Head: final t=511 (odd): h0(511) in i1b x-region, h1(511) in i1a h-region
    if (tid < NB) {
        int gb = gb0 + tid;
        if (gb < BTOT) {
            const float* w2s = smem + OFF_W2S;
            float acc = 0.f;
#pragma unroll
            for (int k = 0; k < 32; k++) acc = fmaf(w2s[k],      i1b[tid * IST + k],      acc);
#pragma unroll
            for (int k = 0; k < 32; k++) acc = fmaf(w2s[32 + k], i1a[tid * IST + 36 + k], acc);
            out[gb] = acc + b2[0];
        }
    }
}

extern "C" void kernel_launch(void* const* d_in, const int* in_sizes, int n_in,
                              void* d_out, int out_size) {
    const float* tensor = (const float*)d_in[0];
    const float* w1     = (const float*)d_in[1];
    const float* b1     = (const float*)d_in[2];
    const float* Wih0   = (const float*)d_in[3];
    const float* Whh0   = (const float*)d_in[4];
    const float* bih0   = (const float*)d_in[5];
    const float* bhh0   = (const float*)d_in[6];
    const float* Wih1   = (const float*)d_in[7];
    const float* Whh1   = (const float*)d_in[8];
    const float* bih1   = (const float*)d_in[9];
    const float* bhh1   = (const float*)d_in[10];
    const float* w2     = (const float*)d_in[11];
    const float* b2     = (const float*)d_in[12];
    float* out = (float*)d_out;

    int Btot = in_sizes[0] / TSTEPS;       // 4096
    int grid = (Btot + NB - 1) / NB;       // 147 CTAs

    cudaFuncSetAttribute(lstm_fused_kernel,
                         cudaFuncAttributeMaxDynamicSharedMemorySize, SMEM_BYTES);
    lstm_fused_kernel<<<grid, NTHREADS, SMEM_BYTES>>>(
        tensor, w1, b1, Wih0, Whh0, bih0, bhh0,
        Wih1, Whh1, bih1, bhh1, w2, b2, out);
}